// round 12
// baseline (speedup 1.0000x reference)
#include <cuda_runtime.h>
#include <stdint.h>

#define BNUM 32
#define PNUM 8732
#define CFG  20
#define NPAIR (BNUM*CFG)
#define KPRE 256
#define TOPK 200
#define CAP  1024
#define QCAP 1024
#define NT   512
#define TSAMP 128

typedef unsigned long long u64;

// per-half named barrier (ids 1 and 2), 256 threads each
#define BARH() asm volatile("bar.sync %0, %1;" :: "r"(h + 1), "r"(256) : "memory")

// ------------------------------------------------------------------
__device__ uint32_t g_keys[(size_t)NPAIR * PNUM];   // mono(prob) per [b][c][p]

__device__ __forceinline__ uint32_t mono(float f) {
    uint32_t u = __float_as_uint(f);
    return (u & 0x80000000u) ? ~u : (u | 0x80000000u);
}
__device__ __forceinline__ float unmono(uint32_t k) {
    uint32_t u = (k & 0x80000000u) ? (k ^ 0x80000000u) : ~k;
    return __uint_as_float(u);
}

// ------------------------------------------------------------------
// kernel 1: softmax only (exact jax.nn.softmax order) -> mono keys
// ------------------------------------------------------------------
__global__ void prep_kernel(const float* __restrict__ conf) {
    int g = blockIdx.x * blockDim.x + threadIdx.x;
    if (g >= BNUM * PNUM) return;
    int b = g / PNUM, p = g % PNUM;

    const float* cp = conf + (size_t)g * 21;
    float x[21];
#pragma unroll
    for (int c = 0; c < 21; c++) x[c] = cp[c];
    float m = x[0];
#pragma unroll
    for (int c = 1; c < 21; c++) m = fmaxf(m, x[c]);
    float e[21];
    float s = 0.f;
#pragma unroll
    for (int c = 0; c < 21; c++) { e[c] = expf(x[c] - m); s += e[c]; }
#pragma unroll
    for (int c = 1; c < 21; c++)
        g_keys[((size_t)b * CFG + (c - 1)) * PNUM + p] = mono(e[c] / s);
}

// ------------------------------------------------------------------
// leader-warp helpers (called by all 32 lanes of a half's warp 0)
// ------------------------------------------------------------------
__device__ __forceinline__ void warp_select(const uint32_t* s_hist,
                                            const uint32_t* s_csum,
                                            uint32_t target, uint32_t n0,
                                            volatile uint32_t* s_sel, int l) {
    uint32_t v[8]; uint32_t tot = 0;
#pragma unroll
    for (int m = 0; m < 8; m++) { v[m] = s_csum[l * 8 + m]; tot += v[m]; }
    uint32_t incl = tot;
#pragma unroll
    for (int o = 1; o < 32; o <<= 1) {
        uint32_t t = __shfl_down_sync(0xFFFFFFFFu, incl, o);
        if (l + o < 32) incl += t;
    }
    uint32_t above = incl - tot;
    if ((above + n0 < target) && (incl + n0 >= target)) {
        uint32_t acc = above + n0;
        int mm = 0;
        for (int m = 7; m >= 0; m--) {
            if (acc + v[m] >= target) { mm = m; break; }
            acc += v[m];
        }
        int chunk = l * 8 + mm;
        int bb = chunk * 8;
        for (int bi = chunk * 8 + 7; bi >= chunk * 8; bi--) {
            uint32_t hh = s_hist[bi];
            if (acc + hh >= target) { bb = bi; break; }
            acc += hh;
        }
        s_sel[0] = (uint32_t)bb; s_sel[1] = acc;
    }
}

__device__ __forceinline__ void warp_select256(const uint32_t* s_hist,
                                               uint32_t target, uint32_t n0,
                                               volatile uint32_t* s_sel, int l) {
    uint32_t v[8]; uint32_t tot = 0;
#pragma unroll
    for (int m = 0; m < 8; m++) { v[m] = s_hist[l * 8 + m]; tot += v[m]; }
    uint32_t incl = tot;
#pragma unroll
    for (int o = 1; o < 32; o <<= 1) {
        uint32_t t = __shfl_down_sync(0xFFFFFFFFu, incl, o);
        if (l + o < 32) incl += t;
    }
    uint32_t above = incl - tot;
    if ((above + n0 < target) && (incl + n0 >= target)) {
        uint32_t acc = above + n0;
        int bb = l * 8;
        for (int m = 7; m >= 0; m--) {
            if (acc + v[m] >= target) { bb = l * 8 + m; break; }
            acc += v[m];
        }
        s_sel[0] = (uint32_t)bb; s_sel[1] = acc;
    }
}

// ------------------------------------------------------------------
// kernel 2: TWO pairs per block, independent pipelines (warps 0-7 / 8-15)
// ------------------------------------------------------------------
__global__ __launch_bounds__(NT, 3) void topk_nms_kernel(float* __restrict__ out,
                                                         const float* __restrict__ loc,
                                                         const float* __restrict__ prior) {
    __shared__ u64      s_h64[2][1024];   // hist(2048 u32) / compact(QCAP u64) / supp matrix
    __shared__ u64      s_cand[2][CAP];
    __shared__ u64      s_key[2][KPRE];   // low 1KB aliased as csum during select
    __shared__ float4   s_box[2][KPRE];
    __shared__ float    s_area[2][KPRE];
    __shared__ uint32_t s_keep[2][8];
    __shared__ uint32_t s_wpre[2][8];
    __shared__ uint32_t s_rowmask[2][8];
    __shared__ uint32_t s_sel[2][2];
    __shared__ uint32_t s_cnt[2];

    const int tid  = threadIdx.x;
    const int h    = tid >> 8;             // half (pipeline) 0/1
    const int ltid = tid & 255;            // thread within half
    const int wid8 = (tid >> 5) & 7;       // warp within half
    const int lane = tid & 31;
    const int pair = blockIdx.x * 2 + h;
    const int b    = pair / CFG;

    uint32_t* s_hist = (uint32_t*)s_h64[h];
    uint32_t* s_csum = (uint32_t*)s_key[h];
    const uint32_t* __restrict__ keys = g_keys + (size_t)pair * PNUM;
    const uint4* __restrict__ keys4 = (const uint4*)keys;
    const int N4 = PNUM / 4;  // 2183

    // ================= sample histogram (25% stride sample, 2184 keys) =================
    {   // zero 2048 u32 = 512 uint4 per half
        uint4* hz = (uint4*)s_hist;
        hz[ltid] = make_uint4(0, 0, 0, 0);
        hz[ltid + 256] = make_uint4(0, 0, 0, 0);
    }
    BARH();
    for (int i = ltid; i < 546; i += 256) {
        uint4 k = keys4[i * 4];
        atomicAdd(&s_hist[k.x >> 21], 1u);
        atomicAdd(&s_hist[k.y >> 21], 1u);
        atomicAdd(&s_hist[k.z >> 21], 1u);
        atomicAdd(&s_hist[k.w >> 21], 1u);
    }
    BARH();
    {
        uint32_t cs = 0;
#pragma unroll
        for (int i = 0; i < 8; i++) cs += s_hist[ltid * 8 + i];
        s_csum[ltid] = cs;
    }
    BARH();
    if (wid8 == 0) warp_select(s_hist, s_csum, TSAMP, 0, s_sel[h], lane);
    BARH();
    const uint32_t T0 = s_sel[h][0] << 21;

    // ============ gather: key >= T0 (per-lane atomics, unroll-2) ============
    if (ltid == 0) s_cnt[h] = 0;
    BARH();
#define TRYPUSH(kk, pp, TH) \
    if ((kk) >= (TH)) { \
        uint32_t pos = atomicAdd(&s_cnt[h], 1u); \
        if (pos < CAP) s_cand[h][pos] = ((u64)(kk) << 32) | (uint32_t)(~(uint32_t)(pp)); }
#define PUSH4(k, p0, TH) \
    TRYPUSH((k).x, (p0), TH); TRYPUSH((k).y, (p0) + 1, TH); \
    TRYPUSH((k).z, (p0) + 2, TH); TRYPUSH((k).w, (p0) + 3, TH);
    {
        int p = ltid;
        for (; p + 256 < N4; p += 512) {
            uint4 ka = keys4[p];
            uint4 kb = keys4[p + 256];
            PUSH4(ka, 4 * p, T0);
            PUSH4(kb, 4 * (p + 256), T0);
        }
        for (; p < N4; p += 256) {
            uint4 k = keys4[p];
            PUSH4(k, 4 * p, T0);
        }
    }
    BARH();
    uint32_t M = s_cnt[h];

    // ================= fallback: exact global select (rare) =================
    if (M < KPRE || M > CAP) {
        for (int i = ltid; i < 2048; i += 256) s_hist[i] = 0;
        BARH();
        for (int p = ltid; p < N4; p += 256) {
            uint4 k = keys4[p];
            atomicAdd(&s_hist[k.x >> 21], 1u);
            atomicAdd(&s_hist[k.y >> 21], 1u);
            atomicAdd(&s_hist[k.z >> 21], 1u);
            atomicAdd(&s_hist[k.w >> 21], 1u);
        }
        BARH();
        {
            uint32_t cs = 0;
#pragma unroll
            for (int i = 0; i < 8; i++) cs += s_hist[ltid * 8 + i];
            s_csum[ltid] = cs;
        }
        BARH();
        if (wid8 == 0) warp_select(s_hist, s_csum, KPRE, 0, s_sel[h], lane);
        BARH();
        uint32_t bbe = s_sel[h][0], n_above = s_sel[h][1];
        uint32_t Te = bbe << 21;
        if (ltid == 0) s_cnt[h] = 0;
        BARH();
        for (int p = ltid; p < N4; p += 256) {
            uint4 k = keys4[p];
            PUSH4(k, 4 * p, Te);
        }
        BARH();
        M = s_cnt[h];
        if (M > CAP) {   // boundary bin too fat: refine globally to 21 bits
            for (int i = ltid; i < 2048; i += 256) s_hist[i] = 0;
            BARH();
            for (int p = ltid; p < PNUM; p += 256) {
                uint32_t k = keys[p];
                if ((k >> 21) == bbe) atomicAdd(&s_hist[(k >> 10) & 0x7FFu], 1u);
            }
            BARH();
            {
                uint32_t cs = 0;
#pragma unroll
                for (int i = 0; i < 8; i++) cs += s_hist[ltid * 8 + i];
                s_csum[ltid] = cs;
            }
            BARH();
            if (wid8 == 0) warp_select(s_hist, s_csum, KPRE, n_above, s_sel[h], lane);
            BARH();
            uint32_t pref21 = (bbe << 11) | s_sel[h][0];
            if (ltid == 0) s_cnt[h] = 0;
            BARH();
            for (int p = ltid; p < PNUM; p += 256) {
                uint32_t k = keys[p];
                if ((k >> 10) >= pref21) {
                    uint32_t pos = atomicAdd(&s_cnt[h], 1u);
                    if (pos < CAP) s_cand[h][pos] = ((u64)k << 32) | (uint32_t)(~(uint32_t)p);
                }
            }
            BARH();
            M = s_cnt[h];
            if (M > CAP) M = CAP;
        }
    }
#undef PUSH4
#undef TRYPUSH

    // ============ in-shared refine, 4 levels x 8-bit digits -> exact F ============
    uint32_t pref = 0, n0 = 0;
#pragma unroll
    for (int lev = 0; lev < 4; lev++) {
        const int sh = 24 - lev * 8;
        s_hist[ltid] = 0;                    // 256 bins
        BARH();
        for (uint32_t i = ltid; i < M; i += 256) {
            uint32_t k = (uint32_t)(s_cand[h][i] >> 32);
            bool match = (lev == 0) || ((k >> (sh + 8)) == pref);
            if (match) atomicAdd(&s_hist[(k >> sh) & 255u], 1u);
        }
        BARH();
        if (wid8 == 0) warp_select256(s_hist, KPRE, n0, s_sel[h], lane);
        BARH();
        pref = (pref << 8) | s_sel[h][0];
        n0 = s_sel[h][1];
        BARH();
    }
    const uint32_t F = pref;

    // ================= compact qualifying (key >= F) into s_h64 =================
    if (ltid == 0) s_cnt[h] = 0;
    BARH();
    for (uint32_t i = ltid; i < M; i += 256) {
        u64 c = s_cand[h][i];
        if ((uint32_t)(c >> 32) >= F) {
            uint32_t pos = atomicAdd(&s_cnt[h], 1u);
            if (pos < QCAP) s_h64[h][pos] = c;
        }
    }
    BARH();
    uint32_t M2 = s_cnt[h]; if (M2 > QCAP) M2 = QCAP;

    // ================= sort: bitonic-256 (generic) or rank-sort (ties) =================
    if (M2 == KPRE) {
        u64 mine = s_h64[h][ltid];
        BARH();
#pragma unroll
        for (uint32_t k = 2; k <= 256; k <<= 1) {
            for (uint32_t j = k >> 1; j >= 1; j >>= 1) {
                u64 other;
                if (j >= 32) {
                    s_key[h][ltid] = mine;
                    BARH();
                    other = s_key[h][ltid ^ j];
                    BARH();
                } else {
                    other = __shfl_xor_sync(0xFFFFFFFFu, mine, j);
                }
                bool lower   = (ltid & j) == 0;
                bool dirDesc = (ltid & k) == 0;
                bool takeMax = (lower == dirDesc);
                u64 mx = mine > other ? mine : other;
                u64 mn = mine > other ? other : mine;
                mine = takeMax ? mx : mn;
            }
        }
        s_key[h][ltid] = mine;
    } else {
        for (uint32_t i = ltid; i < M2; i += 256) {
            u64 mine = s_h64[h][i];
            uint32_t rank = 0;
            for (uint32_t j = 0; j < M2; j++) rank += (s_h64[h][j] > mine);
            if (rank < KPRE) s_key[h][rank] = mine;
        }
    }
    BARH();

    // ======== extract top-256: decode box on demand (exact prep arithmetic) ========
    u64 key = s_key[h][ltid];
    uint32_t idx = ~(uint32_t)key;
    float scv = unmono((uint32_t)(key >> 32));
    float4 bj;
    {
        float4 l  = __ldg((const float4*)loc + (size_t)b * PNUM + idx);
        float4 pr = __ldg((const float4*)prior + idx);
        float cx = pr.x + (l.x * 0.1f) * pr.z;
        float cy = pr.y + (l.y * 0.1f) * pr.w;
        float w  = pr.z * expf(l.z * 0.2f);
        float hh = pr.w * expf(l.w * 0.2f);
        float x1 = cx - w * 0.5f;
        float y1 = cy - hh * 0.5f;
        bj = make_float4(x1, y1, x1 + w, y1 + hh);
    }
    float aj = fmaxf(bj.z - bj.x, 0.f) * fmaxf(bj.w - bj.y, 0.f);
    s_box[h][ltid]  = bj;
    s_area[h][ltid] = aj;
    {
        bool valid = scv > 0.01f;
        uint32_t bal = __ballot_sync(0xFFFFFFFFu, valid);
        if (lane == 0) s_keep[h][wid8] = bal;
    }
    if (ltid < 8) s_rowmask[h][ltid] = 0;
    float* op = out + (size_t)pair * (TOPK * 5);
    {   // float4 zeroing (1000 floats = 250 float4)
        float4* op4 = (float4*)op;
        if (ltid < TOPK * 5 / 4) op4[ltid] = make_float4(0.f, 0.f, 0.f, 0.f);
    }
    uint32_t* s_supp = (uint32_t*)s_h64[h];
    BARH();

    // ===== suppression bitmatrix: balanced schedule, FFMA-band IoU =====
#pragma unroll 1
    for (int g = 0; g < 8; g++) {
        const int    colg = g * 32 + lane;
        const float4 bg   = s_box[h][colg];
        const float  ag   = s_area[h][colg];
        const float  chi  = __fmul_rn(0.310395f, ag);
        const float  clo  = __fmul_rn(0.310295f, ag);
        const int    gbase = g * 32;
        // main rows: i < 32g -> colg > i always (no lane test), 4-wide unrolled
#pragma unroll 1
        for (int t = 0; t < g; t++) {
#pragma unroll
            for (int u = 0; u < 4; u++) {
                const int i = wid8 + t * 32 + u * 8;
                float4 bi = s_box[h][i];
                float wx = fmaxf(fminf(bi.z, bg.z) - fmaxf(bi.x, bg.x), 0.f);
                float wy = fmaxf(fminf(bi.w, bg.w) - fmaxf(bi.y, bg.y), 0.f);
                float inter = __fmul_rn(wx, wy);
                float ai = s_area[h][i];
                bool sup = inter > __fmaf_rn(0.310395f, ai, chi);
                if (!sup && inter >= __fmaf_rn(0.310295f, ai, clo)) {
                    float s  = __fadd_rn(ai, ag);
                    float ut = fmaxf(__fadd_rn(s, -inter), 1e-9f);
                    sup = (inter / ut) > 0.45f;           // exact IEEE path (rare)
                }
                uint32_t bal = __ballot_sync(0xFFFFFFFFu, sup);
                if (lane == 0) {
                    s_supp[i * 8 + g] = bal;
                    if (bal) atomicOr(&s_rowmask[h][i >> 5], 1u << (i & 31));
                }
            }
        }
        // diagonal rows: i in [32g, 32g+32) -> lane test needed
#pragma unroll
        for (int t = 0; t < 4; t++) {
            const int i = gbase + wid8 + t * 8;
            float4 bi = s_box[h][i];
            float wx = fmaxf(fminf(bi.z, bg.z) - fmaxf(bi.x, bg.x), 0.f);
            float wy = fmaxf(fminf(bi.w, bg.w) - fmaxf(bi.y, bg.y), 0.f);
            float inter = __fmul_rn(wx, wy);
            float ai = s_area[h][i];
            bool gt  = colg > i;
            bool sup = gt && (inter > __fmaf_rn(0.310395f, ai, chi));
            if (gt && !sup && inter >= __fmaf_rn(0.310295f, ai, clo)) {
                float s  = __fadd_rn(ai, ag);
                float ut = fmaxf(__fadd_rn(s, -inter), 1e-9f);
                sup = (inter / ut) > 0.45f;
            }
            uint32_t bal = __ballot_sync(0xFFFFFFFFu, sup);
            if (lane == 0) {
                s_supp[i * 8 + g] = bal;
                if (bal) atomicOr(&s_rowmask[h][i >> 5], 1u << (i & 31));
            }
        }
    }
    BARH();

    // ====== sparse greedy scan on the half's warp 0 ======
    if (wid8 == 0) {
        uint32_t kw = (lane < 8) ? s_keep[h][lane] : 0u;
        for (int w8 = 0; w8 < 8; w8++) {
            uint32_t rm = s_rowmask[h][w8];
            while (rm) {
                int bit = __ffs(rm) - 1; rm &= rm - 1;
                int i = w8 * 32 + bit;
                uint32_t w = __shfl_sync(0xFFFFFFFFu, kw, w8);
                uint32_t cur = (lane < 8 && lane >= w8) ? s_supp[i * 8 + lane] : 0u;
                if ((w >> bit) & 1u)
                    kw &= ~cur;
            }
        }
        if (lane < 8) s_keep[h][lane] = kw;
    }
    BARH();

    // ================= compaction + output =================
    if (ltid == 0) {
        uint32_t a = 0;
#pragma unroll
        for (int w2 = 0; w2 < 8; w2++) { s_wpre[h][w2] = a; a += __popc(s_keep[h][w2]); }
    }
    BARH();

    uint32_t kwm = s_keep[h][wid8];
    if ((kwm >> lane) & 1u) {
        uint32_t rank = s_wpre[h][wid8] + __popc(kwm & ((1u << lane) - 1u));
        if (rank < TOPK) {
            float* r = op + (size_t)rank * 5;
            r[0] = scv;
            r[1] = bj.x; r[2] = bj.y; r[3] = bj.z; r[4] = bj.w;
        }
    }
}

// ------------------------------------------------------------------
extern "C" void kernel_launch(void* const* d_in, const int* in_sizes, int n_in,
                              void* d_out, int out_size) {
    const float* loc   = (const float*)d_in[0];
    const float* conf  = (const float*)d_in[1];
    const float* prior = (const float*)d_in[2];
    float* out = (float*)d_out;

    int total = BNUM * PNUM;
    prep_kernel<<<(total + 255) / 256, 256>>>(conf);
    topk_nms_kernel<<<NPAIR / 2, NT>>>(out, loc, prior);
}